// round 2
// baseline (speedup 1.0000x reference)
#include <cuda_runtime.h>
#include <cuda_bf16.h>
#include <math.h>

// ---------------- problem constants ----------------
#define B   64
#define S   128
#define D   64
#define H   256
#define P   1024
#define VR  32000          // VOCAB * REPEAT
#define G4  1024           // 4*H
#define THRESH 0.64f

// ---------------- device scratch (static, allowed) ----------------
__device__ float    g_xt  [2*S*B*D];        // transposed x: [(inp,s,b), d]
__device__ float    g_xg  [2*S*B*G4];       // xg buffer (reused for layer0 and layer1)  64MB
__device__ float    g_hs  [2*S*B*H];        // layer0 hidden states                       16MB
__device__ float    g_hbuf[2*2*B*H];        // h double buffer for scan
__device__ float    g_cat [B*2*H];          // concat(out1,out2) per batch row [64][512]
__device__ float    g_h1  [B*P];
__device__ float    g_h2  [B*P];
__device__ float    g_hbn [B*P];
__device__ int      g_cnt [B];
__device__ unsigned g_bar [8];

// ---------------- helpers ----------------
__device__ __forceinline__ float sigf(float x) { return 1.f / (1.f + __expf(-x)); }

// ---------------- init / finalize ----------------
__global__ void init_kernel() {
    int t = threadIdx.x;
    if (t < 8)  g_bar[t] = 0u;
    if (t < B)  g_cnt[t] = 0;
}

__global__ void finalize_kernel(float* out_tail, int do_write) {
    int b = threadIdx.x;
    if (b < B && do_write) {
        int n = g_cnt[b];
        if (n < 1) n = 1;
        out_tail[b] = (float)n;
    }
}

// ---------------- x transpose: [B,S,D] -> [(inp,s,b),d] ----------------
__global__ void prep_x(const float* __restrict__ x1, const float* __restrict__ x2) {
    int idx = blockIdx.x * blockDim.x + threadIdx.x;   // 2*128*64*64 = 1<<20
    if (idx >= 2*S*B*D) return;
    int d   = idx & 63;
    int b   = (idx >> 6) & 63;
    int s   = (idx >> 12) & 127;
    int inp = idx >> 19;
    const float* x = inp ? x2 : x1;
    g_xt[idx] = x[(b * S + s) * D + d];
}

// ---------------- generic SIMT GEMM:  C[M,N] = epi(A[M,K] @ W[N,K]^T + bias (+bias2)) ----------------
// MODE 0: bias only; 1: exact GELU; 2: resid + relu(v); 3: relu(v) + per-row count(v>THRESH)
template<int MODE>
__global__ void gemm_k(const float* __restrict__ A, const float* __restrict__ W,
                       const float* __restrict__ bias, const float* __restrict__ bias2,
                       const float* __restrict__ resid, float* __restrict__ C,
                       int M, int N, int K, int* __restrict__ cnt) {
    __shared__ float As[16][64];
    __shared__ float Bs[16][64];
    __shared__ int   scnt[64];

    const int t     = threadIdx.x;           // 256
    const int mBase = blockIdx.y * 64;
    const int nBase = blockIdx.x * 64;
    const int lr    = t >> 2;                // 0..63
    const int lk    = (t & 3) * 4;           // 0,4,8,12
    const int tm    = t >> 4;                // 0..15
    const int tn    = t & 15;                // 0..15

    if (MODE == 3 && t < 64) scnt[t] = 0;

    float acc[4][4];
    #pragma unroll
    for (int i = 0; i < 4; i++)
        #pragma unroll
        for (int j = 0; j < 4; j++) acc[i][j] = 0.f;

    for (int kb = 0; kb < K; kb += 16) {
        __syncthreads();
        float4 av = *(const float4*)(A + (size_t)(mBase + lr) * K + kb + lk);
        float4 wv = *(const float4*)(W + (size_t)(nBase + lr) * K + kb + lk);
        As[lk + 0][lr] = av.x; As[lk + 1][lr] = av.y; As[lk + 2][lr] = av.z; As[lk + 3][lr] = av.w;
        Bs[lk + 0][lr] = wv.x; Bs[lk + 1][lr] = wv.y; Bs[lk + 2][lr] = wv.z; Bs[lk + 3][lr] = wv.w;
        __syncthreads();
        #pragma unroll
        for (int k = 0; k < 16; k++) {
            float4 a = *(const float4*)&As[k][tm * 4];
            float4 b = *(const float4*)&Bs[k][tn * 4];
            acc[0][0] = fmaf(a.x, b.x, acc[0][0]); acc[0][1] = fmaf(a.x, b.y, acc[0][1]);
            acc[0][2] = fmaf(a.x, b.z, acc[0][2]); acc[0][3] = fmaf(a.x, b.w, acc[0][3]);
            acc[1][0] = fmaf(a.y, b.x, acc[1][0]); acc[1][1] = fmaf(a.y, b.y, acc[1][1]);
            acc[1][2] = fmaf(a.y, b.z, acc[1][2]); acc[1][3] = fmaf(a.y, b.w, acc[1][3]);
            acc[2][0] = fmaf(a.z, b.x, acc[2][0]); acc[2][1] = fmaf(a.z, b.y, acc[2][1]);
            acc[2][2] = fmaf(a.z, b.z, acc[2][2]); acc[2][3] = fmaf(a.z, b.w, acc[2][3]);
            acc[3][0] = fmaf(a.w, b.x, acc[3][0]); acc[3][1] = fmaf(a.w, b.y, acc[3][1]);
            acc[3][2] = fmaf(a.w, b.z, acc[3][2]); acc[3][3] = fmaf(a.w, b.w, acc[3][3]);
        }
    }

    #pragma unroll
    for (int i = 0; i < 4; i++) {
        int r  = mBase + tm * 4 + i;
        int rc = 0;
        #pragma unroll
        for (int jj = 0; jj < 4; jj++) {
            int n = nBase + tn * 4 + jj;
            float v = acc[i][jj] + bias[n];
            if (bias2) v += bias2[n];
            if (MODE == 1) v = 0.5f * v * (1.f + erff(v * 0.70710678118654752f));
            if (MODE == 2) v = resid[(size_t)r * N + n] + fmaxf(v, 0.f);
            if (MODE == 3) { v = fmaxf(v, 0.f); if (v > THRESH) rc++; }
            C[(size_t)r * N + n] = v;
        }
        if (MODE == 3 && rc) atomicAdd(&scnt[tm * 4 + i], rc);
    }
    if (MODE == 3) {
        __syncthreads();
        if (t < 64 && scnt[t]) atomicAdd(&cnt[mBase + t], scnt[t]);
    }
}

// ---------------- persistent LSTM scan ----------------
// grid: 128 CTAs = inp(2) x bchunk(4: 16 batch rows) x hchunk(16: 16 hidden units)
// block: 128 threads = btile(8: 2 batch rows each) x j(16)
// SMEM: w4[256][16] float4 (gate-packed Whh slice, resident all steps) + h_sm[16][257]
__global__ void lstm_scan(const float* __restrict__ xg, const float* __restrict__ Whh,
                          float* __restrict__ hs_out, float* __restrict__ cat_out) {
    extern __shared__ float smem[];
    float4* w4   = (float4*)smem;                 // [256][16]
    float*  h_sm = smem + 256 * 16 * 4;           // [16][257] padded

    const int t   = threadIdx.x;                  // 128
    const int bt  = t >> 4;                       // 0..7
    const int j   = t & 15;                       // 0..15
    const int bx  = blockIdx.x;                   // 0..127
    const int inp = bx >> 6;
    const int bc  = (bx >> 4) & 3;
    const int hc  = bx & 15;
    const int grp = bx >> 4;                      // 0..7  (inp*4+bc)
    const int jg  = hc * 16 + j;                  // global hidden idx
    const int bl0 = bt * 2;                       // local batch 0..15
    const int b0  = bc * 16 + bl0;                // global batch

    // load gate-packed weight slice: w4[k][j] = (Wi[jg][k], Wf, Wg, Wo)
    for (int k = bt * 32; k < bt * 32 + 32; k++) {
        w4[k * 16 + j] = make_float4(Whh[(0 * H + jg) * H + k],
                                     Whh[(1 * H + jg) * H + k],
                                     Whh[(2 * H + jg) * H + k],
                                     Whh[(3 * H + jg) * H + k]);
    }
    for (int i = t; i < 16 * 257; i += 128) h_sm[i] = 0.f;
    __syncthreads();

    float c0 = 0.f, c1 = 0.f, sum0 = 0.f, sum1 = 0.f;
    float* hb_base = g_hbuf + inp * 2 * B * H;

    for (int s = 0; s < S; s++) {
        float4 a0 = make_float4(0.f, 0.f, 0.f, 0.f);
        float4 a1 = make_float4(0.f, 0.f, 0.f, 0.f);
        const float* hr0 = h_sm + bl0 * 257;
        const float* hr1 = h_sm + (bl0 + 1) * 257;
        #pragma unroll 8
        for (int k = 0; k < H; k++) {
            float4 w = w4[k * 16 + j];
            float ha = hr0[k], hb = hr1[k];
            a0.x = fmaf(w.x, ha, a0.x); a0.y = fmaf(w.y, ha, a0.y);
            a0.z = fmaf(w.z, ha, a0.z); a0.w = fmaf(w.w, ha, a0.w);
            a1.x = fmaf(w.x, hb, a1.x); a1.y = fmaf(w.y, hb, a1.y);
            a1.z = fmaf(w.z, hb, a1.z); a1.w = fmaf(w.w, hb, a1.w);
        }
        const float* xr = xg + ((size_t)(inp * S + s) * B + b0) * G4;
        float gi0 = a0.x + xr[jg];
        float gf0 = a0.y + xr[H + jg];
        float gg0 = a0.z + xr[2 * H + jg];
        float go0 = a0.w + xr[3 * H + jg];
        float gi1 = a1.x + xr[G4 + jg];
        float gf1 = a1.y + xr[G4 + H + jg];
        float gg1 = a1.z + xr[G4 + 2 * H + jg];
        float go1 = a1.w + xr[G4 + 3 * H + jg];

        c0 = sigf(gf0) * c0 + sigf(gi0) * tanhf(gg0);
        float h0 = sigf(go0) * tanhf(c0);
        c1 = sigf(gf1) * c1 + sigf(gi1) * tanhf(gg1);
        float h1 = sigf(go1) * tanhf(c1);

        float* hw = hb_base + (s & 1) * B * H;
        __stcg(&hw[(b0)     * H + jg], h0);
        __stcg(&hw[(b0 + 1) * H + jg], h1);

        if (hs_out) {
            hs_out[((size_t)(inp * S + s) * B + b0) * H + jg]     = h0;
            hs_out[((size_t)(inp * S + s) * B + b0) * H + H + jg] = h1;
        } else {
            sum0 += h0; sum1 += h1;
        }

        __threadfence();
        __syncthreads();
        if (t == 0) {
            atomicAdd(&g_bar[grp], 1u);
            unsigned target = 16u * (unsigned)(s + 1);
            while (*(volatile unsigned*)&g_bar[grp] < target) { }
            __threadfence();
        }
        __syncthreads();

        // reload this CTA's 16 batch rows of h (full H) from L2
        const float4* hr = (const float4*)(hb_base + (s & 1) * B * H + (bc * 16) * H);
        #pragma unroll
        for (int q = 0; q < 8; q++) {
            int fidx = t + 128 * q;          // 0..1023 float4s
            int bl   = fidx >> 6;            // 0..15
            int k4   = fidx & 63;            // 0..63
            float4 v = __ldcg(hr + bl * 64 + k4);
            float* d = h_sm + bl * 257 + k4 * 4;
            d[0] = v.x; d[1] = v.y; d[2] = v.z; d[3] = v.w;
        }
        __syncthreads();
    }

    if (cat_out) {
        cat_out[(b0)     * (2 * H) + inp * H + jg] = sum0;
        cat_out[(b0 + 1) * (2 * H) + inp * H + jg] = sum1;
    }
}

// ---------------- batchnorm over batch (training-mode stats) ----------------
__global__ void bn_kernel(const float* __restrict__ h, const float* __restrict__ gam,
                          const float* __restrict__ bet, float* __restrict__ out) {
    int c = blockIdx.x * blockDim.x + threadIdx.x;
    if (c >= P) return;
    float s = 0.f, s2 = 0.f;
    for (int r = 0; r < B; r++) {
        float v = h[r * P + c];
        s += v; s2 += v * v;
    }
    float mu  = s * (1.f / B);
    float var = s2 * (1.f / B) - mu * mu;
    float inv = rsqrtf(var + 1e-5f) * gam[c];
    float bb  = bet[c];
    for (int r = 0; r < B; r++) {
        out[r * P + c] = (h[r * P + c] - mu) * inv + bb;
    }
}

// ---------------- launcher ----------------
extern "C" void kernel_launch(void* const* d_in, const int* in_sizes, int n_in,
                              void* d_out, int out_size) {
    const float* x1    = (const float*)d_in[0];
    const float* x2    = (const float*)d_in[1];
    const float* Wih0  = (const float*)d_in[2];
    const float* Whh0  = (const float*)d_in[3];
    const float* bih0  = (const float*)d_in[4];
    const float* bhh0  = (const float*)d_in[5];
    const float* Wih1  = (const float*)d_in[6];
    const float* Whh1  = (const float*)d_in[7];
    const float* bih1  = (const float*)d_in[8];
    const float* bhh1  = (const float*)d_in[9];
    const float* fc1_w = (const float*)d_in[10];
    const float* fc1_b = (const float*)d_in[11];
    const float* fc2_w = (const float*)d_in[12];
    const float* fc2_b = (const float*)d_in[13];
    const float* fc3_w = (const float*)d_in[14];
    const float* fc3_b = (const float*)d_in[15];
    const float* bn_g  = (const float*)d_in[16];
    const float* bn_b  = (const float*)d_in[17];
    float* out = (float*)d_out;

    // resolve device-global addresses
    float *p_xt, *p_xg, *p_hs, *p_cat, *p_h1, *p_h2, *p_hbn;
    int   *p_cnt;
    cudaGetSymbolAddress((void**)&p_xt,  g_xt);
    cudaGetSymbolAddress((void**)&p_xg,  g_xg);
    cudaGetSymbolAddress((void**)&p_hs,  g_hs);
    cudaGetSymbolAddress((void**)&p_cat, g_cat);
    cudaGetSymbolAddress((void**)&p_h1,  g_h1);
    cudaGetSymbolAddress((void**)&p_h2,  g_h2);
    cudaGetSymbolAddress((void**)&p_hbn, g_hbn);
    cudaGetSymbolAddress((void**)&p_cnt, g_cnt);

    const int SCAN_SMEM = 256 * 16 * 16 + 16 * 257 * 4;   // 81984 bytes
    cudaFuncSetAttribute(lstm_scan, cudaFuncAttributeMaxDynamicSharedMemorySize, SCAN_SMEM);

    // 1) init barriers/counters
    init_kernel<<<1, 128>>>();

    // 2) transpose x into (inp,s,b,d)
    prep_x<<<(2*S*B*D + 255) / 256, 256>>>(x1, x2);

    // 3) xg0 = xT @ Wih0^T + (bih0 + bhh0)   [16384 x 1024], K=64
    gemm_k<0><<<dim3(G4/64, (2*S*B)/64), 256>>>(p_xt, Wih0, bih0, bhh0, nullptr, p_xg,
                                                2*S*B, G4, D, nullptr);

    // 4) layer-0 recurrence (writes hs)
    lstm_scan<<<128, 128, SCAN_SMEM>>>(p_xg, Whh0, p_hs, nullptr);

    // 5) reset barriers for second scan
    init_kernel<<<1, 128>>>();

    // 6) xg1 = hs @ Wih1^T + (bih1 + bhh1)   [16384 x 1024], K=256
    gemm_k<0><<<dim3(G4/64, (2*S*B)/64), 256>>>(p_hs, Wih1, bih1, bhh1, nullptr, p_xg,
                                                2*S*B, G4, H, nullptr);

    // 7) layer-1 recurrence (accumulates time-sum directly into concat layout)
    lstm_scan<<<128, 128, SCAN_SMEM>>>(p_xg, Whh1, nullptr, p_cat);

    // 8) fc1 + exact GELU: [64 x 1024], K=512
    gemm_k<1><<<dim3(P/64, 1), 256>>>(p_cat, fc1_w, fc1_b, nullptr, nullptr, p_h1,
                                      B, P, 2*H, nullptr);

    // 9) fc2 + relu + residual: [64 x 1024], K=1024
    gemm_k<2><<<dim3(P/64, 1), 256>>>(p_h1, fc2_w, fc2_b, nullptr, p_h1, p_h2,
                                      B, P, P, nullptr);

    // 10) batchnorm (batch statistics)
    bn_kernel<<<(P + 255) / 256, 256>>>(p_h2, bn_g, bn_b, p_hbn);

    // 11) fc3 + relu + threshold count -> scores straight into d_out
    gemm_k<3><<<dim3(VR/64, 1), 256>>>(p_hbn, fc3_w, fc3_b, nullptr, nullptr, out,
                                       B, VR, P, p_cnt);

    // 12) num_select (as float) appended after scores, if the output has room
    int has_tail = (out_size >= B * VR + B) ? 1 : 0;
    finalize_kernel<<<1, 64>>>(out + (size_t)B * VR, has_tail);
}